// round 7
// baseline (speedup 1.0000x reference)
#include <cuda_runtime.h>
#include <cuda_bf16.h>
#include <stdint.h>
#include <math.h>

#define BB   8192
#define HH   512
#define NCC  8704          // S*(2K+1)
#define KP2  1024          // stored K: [hi 512 | lo 512]
#define EPSK 1e-6f

#define ROWB  80           // 64B data + 16B pad per smem row
#define REGN  (128 * ROWB) // 10240 per region (Ahi/Alo/Bhi/Blo)
#define STG   (4 * REGN)   // 40960 per stage
#define NSTG  4
#define DSMEM (NSTG * STG) // 163840

__device__ __align__(128) float         g_net[(size_t)BB * NCC];
__device__ __align__(128) __nv_bfloat16 g_A1[(size_t)BB * KP2];
__device__ __align__(128) __nv_bfloat16 g_A2[(size_t)BB * KP2];
__device__ __align__(128) __nv_bfloat16 g_B1[(size_t)HH * KP2];
__device__ __align__(128) __nv_bfloat16 g_B2[(size_t)NCC * KP2];

// ------------------------------ helpers ------------------------------------
__device__ __forceinline__ uint32_t smem_u32(const void* p) {
    uint32_t a;
    asm("{ .reg .u64 t; cvta.to.shared.u64 t, %1; cvt.u32.u64 %0, t; }" : "=r"(a) : "l"(p));
    return a;
}
#define CP16(dst, src) \
    asm volatile("cp.async.cg.shared.global [%0], [%1], 16;" :: "r"(dst), "l"(src))
#define CP_COMMIT() asm volatile("cp.async.commit_group;" ::: "memory")
#define CP_WAIT2()  asm volatile("cp.async.wait_group 2;" ::: "memory")

__device__ __forceinline__ void ldm_x4(uint32_t* r, uint32_t addr) {
    asm volatile("ldmatrix.sync.aligned.m8n8.x4.shared.b16 {%0,%1,%2,%3}, [%4];"
                 : "=r"(r[0]), "=r"(r[1]), "=r"(r[2]), "=r"(r[3]) : "r"(addr));
}
__device__ __forceinline__ void mma16816(float* c, const uint32_t* a, const uint32_t* b) {
    asm volatile(
        "mma.sync.aligned.m16n8k16.row.col.f32.bf16.bf16.f32 "
        "{%0,%1,%2,%3}, {%4,%5,%6,%7}, {%8,%9}, {%0,%1,%2,%3};"
        : "+f"(c[0]), "+f"(c[1]), "+f"(c[2]), "+f"(c[3])
        : "r"(a[0]), "r"(a[1]), "r"(a[2]), "r"(a[3]), "r"(b[0]), "r"(b[1]));
}
__device__ __forceinline__ float tanh_acc(float x) {
    float y = fminf(fmaxf(2.0f * x, -60.0f), 60.0f);
    float t = __expf(y);
    return __fdividef(t - 1.0f, t + 1.0f);
}

// ---------------------------------------------------------------------------
// C[m][n] = tanh( sum_k A[m][k]*B[n][k] + bias[n] )  via bf16 3-pass split:
//   Ahi*Bhi + Ahi*Blo + Alo*Bhi   (missing AloBlo ~2^-18)
// A,B stored [hi(512)|lo(512)] bf16 row-major (stride KP2).
// CTA 128x128, 8 warps (2m x 4n), warp tile 64x32, BK=32 original-k,
// 4-stage cp.async pipeline, ONE __syncthreads/iter, batched ldsm.
// ---------------------------------------------------------------------------
template <bool SPLIT_OUT>
__global__ __launch_bounds__(256, 1)
void gemm_tc(const __nv_bfloat16* __restrict__ A, const __nv_bfloat16* __restrict__ Bm,
             const float* __restrict__ bias, void* __restrict__ Cv, int Ng)
{
    extern __shared__ char dyn[];
    const uint32_t dynB = smem_u32(dyn);
    const int tid  = threadIdx.x;
    const int lane = tid & 31, w = tid >> 5;
    const int warp_m = w & 1, warp_n = w >> 1;        // 2 x 4
    const int mBase = blockIdx.y * 128, nBase = blockIdx.x * 128;

    const char* Ag = (const char*)(A  + (size_t)mBase * KP2);
    const char* Bg = (const char*)(Bm + (size_t)nBase * KP2);

    const int lrow = tid >> 2;          // 0..63 (+64 second pass)
    const int lch  = (tid & 3) * 16;

#define LOAD_STAGE(c) do {                                                        \
    const uint32_t _s = dynB + ((c) & 3) * STG;                                   \
    const size_t _kb = (size_t)(c) * 64;                                          \
    _Pragma("unroll")                                                             \
    for (int _h = 0; _h < 2; _h++) {                                              \
        const int _r = lrow + _h * 64;                                            \
        const size_t _ra = (size_t)_r * (KP2 * 2);                                \
        CP16(_s + 0*REGN + _r*ROWB + lch, Ag + _ra +        _kb + lch);           \
        CP16(_s + 1*REGN + _r*ROWB + lch, Ag + _ra + 1024 + _kb + lch);           \
        CP16(_s + 2*REGN + _r*ROWB + lch, Bg + _ra +        _kb + lch);           \
        CP16(_s + 3*REGN + _r*ROWB + lch, Bg + _ra + 1024 + _kb + lch);           \
    }                                                                             \
} while (0)

    LOAD_STAGE(0); CP_COMMIT();
    LOAD_STAGE(1); CP_COMMIT();
    LOAD_STAGE(2); CP_COMMIT();

    float acc[4][4][4];
    #pragma unroll
    for (int i = 0; i < 4; i++)
        #pragma unroll
        for (int j = 0; j < 4; j++)
            #pragma unroll
            for (int e = 0; e < 4; e++) acc[i][j][e] = 0.f;

    const int grp = lane >> 3, lr = lane & 7;
    const int a_row = warp_m * 64 + (grp & 1) * 8 + lr;
    const int a_kb  = (grp >> 1) * 16;
    const int b_row = warp_n * 32 + (grp >> 1) * 8 + lr;
    const int b_kb  = (grp & 1) * 16;

    const int NIT = 512 / 32;   // 16
    for (int c = 0; c < NIT; c++) {
        CP_WAIT2();               // stage c resident (c+1, c+2 may be in flight)
        __syncthreads();          // all warps done with stage (c+3)&3's buffer
        if (c + 3 < NIT) LOAD_STAGE(c + 3);
        CP_COMMIT();              // uniform group count

        const uint32_t st = dynB + (c & 3) * STG;

        // ---- batch ALL ldmatrix for this iteration (both kk halves) ----
        uint32_t ahi[2][4][4], alo[2][4][4], bhi[2][4][2], blo[2][4][2];
        #pragma unroll
        for (int kk = 0; kk < 2; kk++) {
            const uint32_t ak = kk * 32 + a_kb;
            const uint32_t bk = kk * 32 + b_kb;
            #pragma unroll
            for (int i = 0; i < 4; i++)
                ldm_x4(ahi[kk][i], st + 0*REGN + (uint32_t)(a_row + i*16)*ROWB + ak);
            #pragma unroll
            for (int p = 0; p < 2; p++) {
                uint32_t r[4];
                ldm_x4(r, st + 2*REGN + (uint32_t)(b_row + p*16)*ROWB + bk);
                bhi[kk][p*2][0] = r[0]; bhi[kk][p*2][1] = r[1];
                bhi[kk][p*2+1][0] = r[2]; bhi[kk][p*2+1][1] = r[3];
            }
            #pragma unroll
            for (int p = 0; p < 2; p++) {
                uint32_t r[4];
                ldm_x4(r, st + 3*REGN + (uint32_t)(b_row + p*16)*ROWB + bk);
                blo[kk][p*2][0] = r[0]; blo[kk][p*2][1] = r[1];
                blo[kk][p*2+1][0] = r[2]; blo[kk][p*2+1][1] = r[3];
            }
            #pragma unroll
            for (int i = 0; i < 4; i++)
                ldm_x4(alo[kk][i], st + 1*REGN + (uint32_t)(a_row + i*16)*ROWB + ak);
        }

        // ---- one long HMMA burst: 192 mma ----
        #pragma unroll
        for (int kk = 0; kk < 2; kk++) {
            #pragma unroll
            for (int i = 0; i < 4; i++)
                #pragma unroll
                for (int j = 0; j < 4; j++)
                    mma16816(acc[i][j], ahi[kk][i], bhi[kk][j]);   // Ahi*Bhi
            #pragma unroll
            for (int i = 0; i < 4; i++)
                #pragma unroll
                for (int j = 0; j < 4; j++)
                    mma16816(acc[i][j], ahi[kk][i], blo[kk][j]);   // Ahi*Blo
            #pragma unroll
            for (int i = 0; i < 4; i++)
                #pragma unroll
                for (int j = 0; j < 4; j++)
                    mma16816(acc[i][j], alo[kk][i], bhi[kk][j]);   // Alo*Bhi
        }
    }
#undef LOAD_STAGE

    // ---------------- epilogue: tanh(acc + bias) ----------------
    #pragma unroll
    for (int j = 0; j < 4; j++) {
        const int col = nBase + warp_n * 32 + j * 8 + (lane & 3) * 2;
        const float bv0 = bias[col], bv1 = bias[col + 1];
        #pragma unroll
        for (int i = 0; i < 4; i++) {
            const int r0 = mBase + warp_m * 64 + i * 16 + (lane >> 2);
            float t00 = tanh_acc(acc[i][j][0] + bv0);
            float t01 = tanh_acc(acc[i][j][1] + bv1);
            float t10 = tanh_acc(acc[i][j][2] + bv0);
            float t11 = tanh_acc(acc[i][j][3] + bv1);
            if (SPLIT_OUT) {
                __nv_bfloat16* O = (__nv_bfloat16*)Cv;
                __nv_bfloat162 h0, l0, h1, l1;
                h0.x = __float2bfloat16(t00); h0.y = __float2bfloat16(t01);
                l0.x = __float2bfloat16(t00 - __bfloat162float(h0.x));
                l0.y = __float2bfloat16(t01 - __bfloat162float(h0.y));
                h1.x = __float2bfloat16(t10); h1.y = __float2bfloat16(t11);
                l1.x = __float2bfloat16(t10 - __bfloat162float(h1.x));
                l1.y = __float2bfloat16(t11 - __bfloat162float(h1.y));
                *(__nv_bfloat162*)&O[(size_t)r0 * KP2 + col]             = h0;
                *(__nv_bfloat162*)&O[(size_t)r0 * KP2 + 512 + col]       = l0;
                *(__nv_bfloat162*)&O[(size_t)(r0 + 8) * KP2 + col]       = h1;
                *(__nv_bfloat162*)&O[(size_t)(r0 + 8) * KP2 + 512 + col] = l1;
            } else {
                float* Cf = (float*)Cv;
                float2 o0, o1;
                o0.x = t00; o0.y = t01; o1.x = t10; o1.y = t11;
                *(float2*)&Cf[(size_t)r0 * Ng + col]       = o0;
                *(float2*)&Cf[(size_t)(r0 + 8) * Ng + col] = o1;
            }
        }
    }
}

// ---------------------------------------------------------------------------
// prep: A1 = [hi | lo] of (x_a - 0.5)
// ---------------------------------------------------------------------------
__global__ void split_x_kernel(const float* __restrict__ src,
                               __nv_bfloat16* __restrict__ dst)
{
    const int idx = blockIdx.x * 256 + threadIdx.x;   // BB*512
    const int b = idx >> 9, s = idx & 511;
    const float v = src[(size_t)b * 1024 + s] - 0.5f;
    const __nv_bfloat16 hi = __float2bfloat16(v);
    __nv_bfloat16* d = dst + (size_t)b * KP2;
    d[s] = hi;
    d[512 + s] = __float2bfloat16(v - __bfloat162float(hi));
}

// prep: B'[n] = [hi | lo] of W[:, n] (transpose + split)
__global__ void wsplit_kernel(const float* __restrict__ W,
                              __nv_bfloat16* __restrict__ Bp, int Ncols)
{
    __shared__ float t[32][33];
    const int n0 = blockIdx.x * 32, k0 = blockIdx.y * 32;
    const int tx = threadIdx.x & 31, ty = threadIdx.x >> 5;   // 32 x 8
    #pragma unroll
    for (int j = 0; j < 4; j++)
        t[ty + 8 * j][tx] = W[(size_t)(k0 + ty + 8 * j) * Ncols + n0 + tx];
    __syncthreads();
    #pragma unroll
    for (int j = 0; j < 4; j++) {
        const int n = n0 + ty + 8 * j;
        const int k = k0 + tx;
        const float v = t[tx][ty + 8 * j];
        const __nv_bfloat16 hi = __float2bfloat16(v);
        __nv_bfloat16* d = Bp + (size_t)n * KP2;
        d[k] = hi;
        d[512 + k] = __float2bfloat16(v - __bfloat162float(hi));
    }
}

// ---------------------------------------------------------------------------
// spline epilogue (validated round 1)
// ---------------------------------------------------------------------------
__global__ __launch_bounds__(512)
void spline_epilogue_kernel(const float* __restrict__ x_input,
                            const float* __restrict__ log_density,
                            const float* __restrict__ net,
                            float* __restrict__ out)
{
    const int b = blockIdx.x;
    const int s = threadIdx.x;

    const float* np = net + (size_t)b * NCC + s * 17;
    float v[17];
    #pragma unroll
    for (int j = 0; j < 17; j++) v[j] = np[j];

    float m = v[9];
    #pragma unroll
    for (int j = 10; j < 17; j++) m = fmaxf(m, v[j]);
    float w[8]; float wsum = 0.f;
    #pragma unroll
    for (int j = 0; j < 8; j++) { w[j] = __expf(v[9 + j] - m); wsum += w[j]; }
    const float winv = 1.f / wsum;
    #pragma unroll
    for (int j = 0; j < 8; j++) w[j] *= winv;

    float eh[9];
    #pragma unroll
    for (int j = 0; j < 9; j++) eh[j] = __expf(v[j]);
    float denom = 0.f;
    #pragma unroll
    for (int i = 0; i < 8; i++) denom += 0.5f * w[i] * (eh[i] + eh[i + 1]);
    const float dinv = 1.f / denom;
    float h[9];
    #pragma unroll
    for (int i = 0; i < 9; i++) h[i] = eh[i] * dinv;

    const float xa = x_input[(size_t)b * 1024 + s];
    const float xb = x_input[(size_t)b * 1024 + 512 + s];

    int cnt = (-EPSK < xb) ? 1 : 0;
    float cs = 0.f;
    #pragma unroll
    for (int i = 0; i < 8; i++) { cs += w[i]; cnt += (cs < xb) ? 1 : 0; }
    int k = cnt - 1;
    k = k < 0 ? 0 : (k > 7 ? 7 : k);

    float xk = 0.f, pk = 0.f, wk = 0.f, hk = 0.f, hk1 = 0.f;
    #pragma unroll
    for (int i = 0; i < 8; i++) {
        const float area = 0.5f * w[i] * (h[i] + h[i + 1]);
        if (i < k)  { xk += w[i]; pk += area; }
        if (i == k) { wk = w[i]; hk = h[i]; hk1 = h[i + 1]; }
    }
    if (k == 0) xk = -EPSK;

    const float alpha = (xb - xk) / wk;
    const float phib  = pk + alpha * hk * wk + 0.5f * alpha * alpha * (hk1 - hk) * wk;
    const float lt    = __logf(fmaf(alpha, (hk1 - hk), hk));

    out[(size_t)b * 1024 + s]       = xa;
    out[(size_t)b * 1024 + 512 + s] = phib;

    __shared__ float red[16];
    float sum = lt;
    #pragma unroll
    for (int o = 16; o > 0; o >>= 1) sum += __shfl_xor_sync(0xffffffffu, sum, o);
    const int lane = s & 31, wid = s >> 5;
    if (lane == 0) red[wid] = sum;
    __syncthreads();
    if (s < 16) {
        float t = red[s];
        #pragma unroll
        for (int o = 8; o > 0; o >>= 1) t += __shfl_xor_sync(0xffffu, t, o);
        if (s == 0) out[(size_t)BB * 1024 + b] = log_density[b] - t;
    }
}

// ---------------------------------------------------------------------------
extern "C" void kernel_launch(void* const* d_in, const int* in_sizes, int n_in,
                              void* d_out, int out_size)
{
    const float* x  = (const float*)d_in[0];
    const float* ld = (const float*)d_in[1];
    const float* W1 = (const float*)d_in[2];
    const float* b1 = (const float*)d_in[3];
    const float* W2 = (const float*)d_in[4];
    const float* b2 = (const float*)d_in[5];
    float* out = (float*)d_out;

    float* net;
    __nv_bfloat16 *A1, *A2, *B1, *B2;
    cudaGetSymbolAddress((void**)&net, g_net);
    cudaGetSymbolAddress((void**)&A1, g_A1);
    cudaGetSymbolAddress((void**)&A2, g_A2);
    cudaGetSymbolAddress((void**)&B1, g_B1);
    cudaGetSymbolAddress((void**)&B2, g_B2);

    cudaFuncSetAttribute(gemm_tc<true>,  cudaFuncAttributeMaxDynamicSharedMemorySize, DSMEM);
    cudaFuncSetAttribute(gemm_tc<false>, cudaFuncAttributeMaxDynamicSharedMemorySize, DSMEM);

    split_x_kernel<<<BB * 512 / 256, 256>>>(x, A1);
    wsplit_kernel<<<dim3(HH / 32, 512 / 32), 256>>>(W1, B1, HH);
    wsplit_kernel<<<dim3(NCC / 32, 512 / 32), 256>>>(W2, B2, NCC);

    // A2 = split(tanh((x_a-0.5) @ W1 + b1))   (fused split epilogue)
    gemm_tc<true><<<dim3(HH / 128, BB / 128), 256, DSMEM>>>(A1, B1, b1, A2, HH);
    // net = tanh(hid @ W2 + b2)
    gemm_tc<false><<<dim3(NCC / 128, BB / 128), 256, DSMEM>>>(A2, B2, b2, net, NCC);

    spline_epilogue_kernel<<<BB, 512>>>(x, ld, net, out);
}

// round 8
// speedup vs baseline: 1.0649x; 1.0649x over previous
#include <cuda_runtime.h>
#include <cuda_bf16.h>
#include <stdint.h>
#include <math.h>

#define BB   8192
#define HH   512
#define NCC  8704          // S*(2K+1)
#define KP2  1024          // stored K: [hi 512 | lo 512]
#define EPSK 1e-6f

#define ROWB  80                    // 64B data + 16B pad per smem row
#define AHI   0
#define ALO   (256 * ROWB)          // 20480
#define BHI   (512 * ROWB)          // 40960
#define BLO   (512 * ROWB + 128 * ROWB)
#define STG   (768 * ROWB)          // 61440 per stage
#define NSTG  3
#define DSMEM (NSTG * STG)          // 184320

__device__ __align__(128) float         g_net[(size_t)BB * NCC];
__device__ __align__(128) __nv_bfloat16 g_A1[(size_t)BB * KP2];
__device__ __align__(128) __nv_bfloat16 g_A2[(size_t)BB * KP2];
__device__ __align__(128) __nv_bfloat16 g_B1[(size_t)HH * KP2];
__device__ __align__(128) __nv_bfloat16 g_B2[(size_t)NCC * KP2];

// ------------------------------ helpers ------------------------------------
__device__ __forceinline__ uint32_t smem_u32(const void* p) {
    uint32_t a;
    asm("{ .reg .u64 t; cvta.to.shared.u64 t, %1; cvt.u32.u64 %0, t; }" : "=r"(a) : "l"(p));
    return a;
}
#define CP16(dst, src) \
    asm volatile("cp.async.cg.shared.global [%0], [%1], 16;" :: "r"(dst), "l"(src))
#define CP_COMMIT() asm volatile("cp.async.commit_group;" ::: "memory")
#define CP_WAIT1()  asm volatile("cp.async.wait_group 1;" ::: "memory")

__device__ __forceinline__ void ldm_x4(uint32_t* r, uint32_t addr) {
    asm volatile("ldmatrix.sync.aligned.m8n8.x4.shared.b16 {%0,%1,%2,%3}, [%4];"
                 : "=r"(r[0]), "=r"(r[1]), "=r"(r[2]), "=r"(r[3]) : "r"(addr));
}
__device__ __forceinline__ void mma16816(float* c, const uint32_t* a, const uint32_t* b) {
    asm volatile(
        "mma.sync.aligned.m16n8k16.row.col.f32.bf16.bf16.f32 "
        "{%0,%1,%2,%3}, {%4,%5,%6,%7}, {%8,%9}, {%0,%1,%2,%3};"
        : "+f"(c[0]), "+f"(c[1]), "+f"(c[2]), "+f"(c[3])
        : "r"(a[0]), "r"(a[1]), "r"(a[2]), "r"(a[3]), "r"(b[0]), "r"(b[1]));
}
__device__ __forceinline__ float tanh_acc(float x) {
    float y = fminf(fmaxf(2.0f * x, -60.0f), 60.0f);
    float t = __expf(y);
    return __fdividef(t - 1.0f, t + 1.0f);
}

// ---------------------------------------------------------------------------
// C[m][n] = tanh( sum_k A[m][k]*B[n][k] + bias[n] )  via bf16 3-pass split:
//   Ahi*Bhi + Ahi*Blo + Alo*Bhi   (missing AloBlo ~2^-18)
// A,B stored [hi(512)|lo(512)] bf16 row-major (stride KP2).
// CTA 256x128, 512 threads, 16 warps (8m x 2n), warp tile 32x64, BK=32,
// 3-stage cp.async pipeline, ONE __syncthreads per iteration.
// ---------------------------------------------------------------------------
template <bool SPLIT_OUT>
__global__ __launch_bounds__(512, 1)
void gemm_tc(const __nv_bfloat16* __restrict__ A, const __nv_bfloat16* __restrict__ Bm,
             const float* __restrict__ bias, void* __restrict__ Cv, int Ng)
{
    extern __shared__ char dyn[];
    const uint32_t dynB = smem_u32(dyn);
    const int tid  = threadIdx.x;
    const int lane = tid & 31, w = tid >> 5;
    const int warp_m = w & 7, warp_n = w >> 3;        // 8 x 2
    const int mBase = blockIdx.y * 256, nBase = blockIdx.x * 128;

    const char* Ag = (const char*)(A  + (size_t)mBase * KP2);
    const char* Bg = (const char*)(Bm + (size_t)nBase * KP2);

    const int lrow = tid >> 2;          // 0..127
    const int lch  = (tid & 3) * 16;

#define LOAD_STAGE(c) do {                                                        \
    const uint32_t _s = dynB + ((c) % 3) * STG;                                   \
    const size_t _kb = (size_t)(c) * 64;                                          \
    _Pragma("unroll")                                                             \
    for (int _h = 0; _h < 2; _h++) {                                              \
        const int _r = lrow + _h * 128;                                           \
        const size_t _ra = (size_t)_r * (KP2 * 2);                                \
        CP16(_s + AHI + _r * ROWB + lch, Ag + _ra +        _kb + lch);            \
        CP16(_s + ALO + _r * ROWB + lch, Ag + _ra + 1024 + _kb + lch);            \
    }                                                                             \
    {                                                                             \
        const size_t _rb = (size_t)lrow * (KP2 * 2);                              \
        CP16(_s + BHI + lrow * ROWB + lch, Bg + _rb +        _kb + lch);          \
        CP16(_s + BLO + lrow * ROWB + lch, Bg + _rb + 1024 + _kb + lch);          \
    }                                                                             \
} while (0)

    LOAD_STAGE(0); CP_COMMIT();
    LOAD_STAGE(1); CP_COMMIT();

    float acc[2][8][4];
    #pragma unroll
    for (int i = 0; i < 2; i++)
        #pragma unroll
        for (int j = 0; j < 8; j++)
            #pragma unroll
            for (int e = 0; e < 4; e++) acc[i][j][e] = 0.f;

    const int grp = lane >> 3, lr = lane & 7;
    const int a_row = warp_m * 32 + (grp & 1) * 8 + lr;
    const int a_kb  = (grp >> 1) * 16;
    const int b_row = warp_n * 64 + (grp >> 1) * 8 + lr;
    const int b_kb  = (grp & 1) * 16;

    const int NIT = 512 / 32;   // 16
    for (int c = 0; c < NIT; c++) {
        CP_WAIT1();               // stage c resident (c+1 in flight)
        __syncthreads();          // buffer (c+2)%3 free (consumed at iter c-1)
        if (c + 2 < NIT) LOAD_STAGE(c + 2);
        CP_COMMIT();              // uniform group count

        const uint32_t st = dynB + (c % 3) * STG;

        #pragma unroll
        for (int kk = 0; kk < 2; kk++) {
            const uint32_t ak = kk * 32 + a_kb;
            const uint32_t bk = kk * 32 + b_kb;
            uint32_t ahi[2][4], alo[2][4], bhi[8][2], blo[8][2];

            #pragma unroll
            for (int i = 0; i < 2; i++)
                ldm_x4(ahi[i], st + AHI + (uint32_t)(a_row + i * 16) * ROWB + ak);
            #pragma unroll
            for (int p = 0; p < 4; p++) {
                uint32_t r[4];
                ldm_x4(r, st + BHI + (uint32_t)(b_row + p * 16) * ROWB + bk);
                bhi[p * 2][0] = r[0]; bhi[p * 2][1] = r[1];
                bhi[p * 2 + 1][0] = r[2]; bhi[p * 2 + 1][1] = r[3];
            }
            #pragma unroll
            for (int i = 0; i < 2; i++)
                #pragma unroll
                for (int j = 0; j < 8; j++)
                    mma16816(acc[i][j], ahi[i], bhi[j]);      // Ahi*Bhi

            #pragma unroll
            for (int p = 0; p < 4; p++) {
                uint32_t r[4];
                ldm_x4(r, st + BLO + (uint32_t)(b_row + p * 16) * ROWB + bk);
                blo[p * 2][0] = r[0]; blo[p * 2][1] = r[1];
                blo[p * 2 + 1][0] = r[2]; blo[p * 2 + 1][1] = r[3];
            }
            #pragma unroll
            for (int i = 0; i < 2; i++)
                #pragma unroll
                for (int j = 0; j < 8; j++)
                    mma16816(acc[i][j], ahi[i], blo[j]);      // Ahi*Blo

            #pragma unroll
            for (int i = 0; i < 2; i++)
                ldm_x4(alo[i], st + ALO + (uint32_t)(a_row + i * 16) * ROWB + ak);
            #pragma unroll
            for (int i = 0; i < 2; i++)
                #pragma unroll
                for (int j = 0; j < 8; j++)
                    mma16816(acc[i][j], alo[i], bhi[j]);      // Alo*Bhi
        }
    }
#undef LOAD_STAGE

    // ---------------- epilogue: tanh(acc + bias) ----------------
    #pragma unroll
    for (int j = 0; j < 8; j++) {
        const int col = nBase + warp_n * 64 + j * 8 + (lane & 3) * 2;
        const float bv0 = bias[col], bv1 = bias[col + 1];
        #pragma unroll
        for (int i = 0; i < 2; i++) {
            const int r0 = mBase + warp_m * 32 + i * 16 + (lane >> 2);
            float t00 = tanh_acc(acc[i][j][0] + bv0);
            float t01 = tanh_acc(acc[i][j][1] + bv1);
            float t10 = tanh_acc(acc[i][j][2] + bv0);
            float t11 = tanh_acc(acc[i][j][3] + bv1);
            if (SPLIT_OUT) {
                __nv_bfloat16* O = (__nv_bfloat16*)Cv;
                __nv_bfloat162 h0, l0, h1, l1;
                h0.x = __float2bfloat16(t00); h0.y = __float2bfloat16(t01);
                l0.x = __float2bfloat16(t00 - __bfloat162float(h0.x));
                l0.y = __float2bfloat16(t01 - __bfloat162float(h0.y));
                h1.x = __float2bfloat16(t10); h1.y = __float2bfloat16(t11);
                l1.x = __float2bfloat16(t10 - __bfloat162float(h1.x));
                l1.y = __float2bfloat16(t11 - __bfloat162float(h1.y));
                *(__nv_bfloat162*)&O[(size_t)r0 * KP2 + col]             = h0;
                *(__nv_bfloat162*)&O[(size_t)r0 * KP2 + 512 + col]       = l0;
                *(__nv_bfloat162*)&O[(size_t)(r0 + 8) * KP2 + col]       = h1;
                *(__nv_bfloat162*)&O[(size_t)(r0 + 8) * KP2 + 512 + col] = l1;
            } else {
                float* Cf = (float*)Cv;
                float2 o0, o1;
                o0.x = t00; o0.y = t01; o1.x = t10; o1.y = t11;
                *(float2*)&Cf[(size_t)r0 * Ng + col]       = o0;
                *(float2*)&Cf[(size_t)(r0 + 8) * Ng + col] = o1;
            }
        }
    }
}

// ---------------------------------------------------------------------------
// prep: A1 = [hi | lo] of (x_a - 0.5)
// ---------------------------------------------------------------------------
__global__ void split_x_kernel(const float* __restrict__ src,
                               __nv_bfloat16* __restrict__ dst)
{
    const int idx = blockIdx.x * 256 + threadIdx.x;   // BB*512
    const int b = idx >> 9, s = idx & 511;
    const float v = src[(size_t)b * 1024 + s] - 0.5f;
    const __nv_bfloat16 hi = __float2bfloat16(v);
    __nv_bfloat16* d = dst + (size_t)b * KP2;
    d[s] = hi;
    d[512 + s] = __float2bfloat16(v - __bfloat162float(hi));
}

// prep: B'[n] = [hi | lo] of W[:, n] (transpose + split)
__global__ void wsplit_kernel(const float* __restrict__ W,
                              __nv_bfloat16* __restrict__ Bp, int Ncols)
{
    __shared__ float t[32][33];
    const int n0 = blockIdx.x * 32, k0 = blockIdx.y * 32;
    const int tx = threadIdx.x & 31, ty = threadIdx.x >> 5;   // 32 x 8
    #pragma unroll
    for (int j = 0; j < 4; j++)
        t[ty + 8 * j][tx] = W[(size_t)(k0 + ty + 8 * j) * Ncols + n0 + tx];
    __syncthreads();
    #pragma unroll
    for (int j = 0; j < 4; j++) {
        const int n = n0 + ty + 8 * j;
        const int k = k0 + tx;
        const float v = t[tx][ty + 8 * j];
        const __nv_bfloat16 hi = __float2bfloat16(v);
        __nv_bfloat16* d = Bp + (size_t)n * KP2;
        d[k] = hi;
        d[512 + k] = __float2bfloat16(v - __bfloat162float(hi));
    }
}

// ---------------------------------------------------------------------------
// spline epilogue (validated round 1)
// ---------------------------------------------------------------------------
__global__ __launch_bounds__(512)
void spline_epilogue_kernel(const float* __restrict__ x_input,
                            const float* __restrict__ log_density,
                            const float* __restrict__ net,
                            float* __restrict__ out)
{
    const int b = blockIdx.x;
    const int s = threadIdx.x;

    const float* np = net + (size_t)b * NCC + s * 17;
    float v[17];
    #pragma unroll
    for (int j = 0; j < 17; j++) v[j] = np[j];

    float m = v[9];
    #pragma unroll
    for (int j = 10; j < 17; j++) m = fmaxf(m, v[j]);
    float w[8]; float wsum = 0.f;
    #pragma unroll
    for (int j = 0; j < 8; j++) { w[j] = __expf(v[9 + j] - m); wsum += w[j]; }
    const float winv = 1.f / wsum;
    #pragma unroll
    for (int j = 0; j < 8; j++) w[j] *= winv;

    float eh[9];
    #pragma unroll
    for (int j = 0; j < 9; j++) eh[j] = __expf(v[j]);
    float denom = 0.f;
    #pragma unroll
    for (int i = 0; i < 8; i++) denom += 0.5f * w[i] * (eh[i] + eh[i + 1]);
    const float dinv = 1.f / denom;
    float h[9];
    #pragma unroll
    for (int i = 0; i < 9; i++) h[i] = eh[i] * dinv;

    const float xa = x_input[(size_t)b * 1024 + s];
    const float xb = x_input[(size_t)b * 1024 + 512 + s];

    int cnt = (-EPSK < xb) ? 1 : 0;
    float cs = 0.f;
    #pragma unroll
    for (int i = 0; i < 8; i++) { cs += w[i]; cnt += (cs < xb) ? 1 : 0; }
    int k = cnt - 1;
    k = k < 0 ? 0 : (k > 7 ? 7 : k);

    float xk = 0.f, pk = 0.f, wk = 0.f, hk = 0.f, hk1 = 0.f;
    #pragma unroll
    for (int i = 0; i < 8; i++) {
        const float area = 0.5f * w[i] * (h[i] + h[i + 1]);
        if (i < k)  { xk += w[i]; pk += area; }
        if (i == k) { wk = w[i]; hk = h[i]; hk1 = h[i + 1]; }
    }
    if (k == 0) xk = -EPSK;

    const float alpha = (xb - xk) / wk;
    const float phib  = pk + alpha * hk * wk + 0.5f * alpha * alpha * (hk1 - hk) * wk;
    const float lt    = __logf(fmaf(alpha, (hk1 - hk), hk));

    out[(size_t)b * 1024 + s]       = xa;
    out[(size_t)b * 1024 + 512 + s] = phib;

    __shared__ float red[16];
    float sum = lt;
    #pragma unroll
    for (int o = 16; o > 0; o >>= 1) sum += __shfl_xor_sync(0xffffffffu, sum, o);
    const int lane = s & 31, wid = s >> 5;
    if (lane == 0) red[wid] = sum;
    __syncthreads();
    if (s < 16) {
        float t = red[s];
        #pragma unroll
        for (int o = 8; o > 0; o >>= 1) t += __shfl_xor_sync(0xffffu, t, o);
        if (s == 0) out[(size_t)BB * 1024 + b] = log_density[b] - t;
    }
}

// ---------------------------------------------------------------------------
extern "C" void kernel_launch(void* const* d_in, const int* in_sizes, int n_in,
                              void* d_out, int out_size)
{
    const float* x  = (const float*)d_in[0];
    const float* ld = (const float*)d_in[1];
    const float* W1 = (const float*)d_in[2];
    const float* b1 = (const float*)d_in[3];
    const float* W2 = (const float*)d_in[4];
    const float* b2 = (const float*)d_in[5];
    float* out = (float*)d_out;

    float* net;
    __nv_bfloat16 *A1, *A2, *B1, *B2;
    cudaGetSymbolAddress((void**)&net, g_net);
    cudaGetSymbolAddress((void**)&A1, g_A1);
    cudaGetSymbolAddress((void**)&A2, g_A2);
    cudaGetSymbolAddress((void**)&B1, g_B1);
    cudaGetSymbolAddress((void**)&B2, g_B2);

    cudaFuncSetAttribute(gemm_tc<true>,  cudaFuncAttributeMaxDynamicSharedMemorySize, DSMEM);
    cudaFuncSetAttribute(gemm_tc<false>, cudaFuncAttributeMaxDynamicSharedMemorySize, DSMEM);

    split_x_kernel<<<BB * 512 / 256, 256>>>(x, A1);
    wsplit_kernel<<<dim3(HH / 32, 512 / 32), 256>>>(W1, B1, HH);
    wsplit_kernel<<<dim3(NCC / 32, 512 / 32), 256>>>(W2, B2, NCC);

    // A2 = split(tanh((x_a-0.5) @ W1 + b1))   (fused split epilogue)
    gemm_tc<true><<<dim3(HH / 128, BB / 256), 512, DSMEM>>>(A1, B1, b1, A2, HH);
    // net = tanh(hid @ W2 + b2)
    gemm_tc<false><<<dim3(NCC / 128, BB / 256), 512, DSMEM>>>(A2, B2, b2, net, NCC);

    spline_epilogue_kernel<<<BB, 512>>>(x, ld, net, out);
}

// round 9
// speedup vs baseline: 1.4967x; 1.4055x over previous
#include <cuda_runtime.h>
#include <cuda_fp16.h>
#include <stdint.h>
#include <math.h>

#define BB   8192
#define HH   512
#define NCC  8704          // S*(2K+1)
#define KP2  1024          // A storage: [hi 512 | lo 512] fp16
#define KB1  512           // B storage: single fp16
#define EPSK 1e-6f

#define ROWB  80                 // 64B data + 16B pad (conflict-free ldsm pitch)
#define AHI   0
#define ALO   (128 * ROWB)       // 10240
#define BRG   (256 * ROWB)       // 20480
#define STG   (384 * ROWB)       // 30720 per stage
#define NSTG  3
#define DSMEM (NSTG * STG)       // 92160  (x2 CTAs/SM = 184320 < 228K)

__device__ __align__(128) float  g_net[(size_t)BB * NCC];
__device__ __align__(128) __half g_A1[(size_t)BB * KP2];
__device__ __align__(128) __half g_A2[(size_t)BB * KP2];
__device__ __align__(128) __half g_B1[(size_t)HH * KB1];
__device__ __align__(128) __half g_B2[(size_t)NCC * KB1];

// ------------------------------ helpers ------------------------------------
__device__ __forceinline__ uint32_t smem_u32(const void* p) {
    uint32_t a;
    asm("{ .reg .u64 t; cvta.to.shared.u64 t, %1; cvt.u32.u64 %0, t; }" : "=r"(a) : "l"(p));
    return a;
}
#define CP16(dst, src) \
    asm volatile("cp.async.cg.shared.global [%0], [%1], 16;" :: "r"(dst), "l"(src))
#define CP_COMMIT() asm volatile("cp.async.commit_group;" ::: "memory")
#define CP_WAIT1()  asm volatile("cp.async.wait_group 1;" ::: "memory")

__device__ __forceinline__ void ldm_x4(uint32_t* r, uint32_t addr) {
    asm volatile("ldmatrix.sync.aligned.m8n8.x4.shared.b16 {%0,%1,%2,%3}, [%4];"
                 : "=r"(r[0]), "=r"(r[1]), "=r"(r[2]), "=r"(r[3]) : "r"(addr));
}
__device__ __forceinline__ void mma16816(float* c, const uint32_t* a, const uint32_t* b) {
    asm volatile(
        "mma.sync.aligned.m16n8k16.row.col.f32.f16.f16.f32 "
        "{%0,%1,%2,%3}, {%4,%5,%6,%7}, {%8,%9}, {%0,%1,%2,%3};"
        : "+f"(c[0]), "+f"(c[1]), "+f"(c[2]), "+f"(c[3])
        : "r"(a[0]), "r"(a[1]), "r"(a[2]), "r"(a[3]), "r"(b[0]), "r"(b[1]));
}
__device__ __forceinline__ float tanh_acc(float x) {
    float y = fminf(fmaxf(2.0f * x, -60.0f), 60.0f);
    float t = __expf(y);
    return __fdividef(t - 1.0f, t + 1.0f);
}

// ---------------------------------------------------------------------------
// C[m][n] = tanh( sum_k A[m][k]*B[n][k] + bias[n] )  via fp16 2-pass split:
//   (Ahi + Alo) * B_fp16   — error only from B's fp16 rounding (~2^-12).
// A stored [hi(512)|lo(512)] fp16 (stride KP2); B stored fp16 (stride KB1).
// CTA 128x128, 256 thr, 8 warps (2m x 4n), warp tile 64x32, BK=32,
// 3-stage cp.async pipeline, ONE __syncthreads per iteration, 2 CTAs/SM.
// ---------------------------------------------------------------------------
template <bool SPLIT_OUT>
__global__ __launch_bounds__(256, 2)
void gemm_tc(const __half* __restrict__ A, const __half* __restrict__ Bm,
             const float* __restrict__ bias, void* __restrict__ Cv, int Ng)
{
    extern __shared__ char dyn[];
    const uint32_t dynB = smem_u32(dyn);
    const int tid  = threadIdx.x;
    const int lane = tid & 31, w = tid >> 5;
    const int warp_m = w & 1, warp_n = w >> 1;        // 2 x 4
    const int mBase = blockIdx.y * 128, nBase = blockIdx.x * 128;

    const char* Ag = (const char*)(A  + (size_t)mBase * KP2);
    const char* Bg = (const char*)(Bm + (size_t)nBase * KB1);

    const int lrow = tid >> 2;          // 0..63 (+64 second pass)
    const int lch  = (tid & 3) * 16;    // 4 thr x 16B = 64B = BK

#define LOAD_STAGE(c) do {                                                        \
    const uint32_t _s = dynB + ((c) % 3) * STG;                                   \
    const size_t _kb = (size_t)(c) * 64;                                          \
    _Pragma("unroll")                                                             \
    for (int _h = 0; _h < 2; _h++) {                                              \
        const int _r = lrow + _h * 64;                                            \
        const size_t _ra = (size_t)_r * (KP2 * 2);                                \
        CP16(_s + AHI + _r * ROWB + lch, Ag + _ra +        _kb + lch);            \
        CP16(_s + ALO + _r * ROWB + lch, Ag + _ra + 1024 + _kb + lch);            \
        CP16(_s + BRG + _r * ROWB + lch, Bg + (size_t)_r * (KB1 * 2) + _kb + lch);\
    }                                                                             \
} while (0)

    LOAD_STAGE(0); CP_COMMIT();
    LOAD_STAGE(1); CP_COMMIT();

    float acc[4][4][4];
    #pragma unroll
    for (int i = 0; i < 4; i++)
        #pragma unroll
        for (int j = 0; j < 4; j++)
            #pragma unroll
            for (int e = 0; e < 4; e++) acc[i][j][e] = 0.f;

    const int grp = lane >> 3, lr = lane & 7;
    const int a_row = warp_m * 64 + (grp & 1) * 8 + lr;
    const int a_kb  = (grp >> 1) * 16;
    const int b_row = warp_n * 32 + (grp >> 1) * 8 + lr;
    const int b_kb  = (grp & 1) * 16;

    const int NIT = 512 / 32;   // 16
    for (int c = 0; c < NIT; c++) {
        CP_WAIT1();               // stage c resident (c+1 in flight)
        __syncthreads();          // buffer (c+2)%3 free (consumed at iter c-1)
        if (c + 2 < NIT) LOAD_STAGE(c + 2);
        CP_COMMIT();              // uniform group count

        const uint32_t st = dynB + (c % 3) * STG;

        #pragma unroll
        for (int kk = 0; kk < 2; kk++) {
            const uint32_t ak = kk * 32 + a_kb;
            const uint32_t bk = kk * 32 + b_kb;
            uint32_t ahi[4][4], alo[4][4], b[4][2];

            #pragma unroll
            for (int i = 0; i < 4; i++)
                ldm_x4(ahi[i], st + AHI + (uint32_t)(a_row + i * 16) * ROWB + ak);
            #pragma unroll
            for (int p = 0; p < 2; p++) {
                uint32_t r[4];
                ldm_x4(r, st + BRG + (uint32_t)(b_row + p * 16) * ROWB + bk);
                b[p * 2][0] = r[0]; b[p * 2][1] = r[1];
                b[p * 2 + 1][0] = r[2]; b[p * 2 + 1][1] = r[3];
            }
            #pragma unroll
            for (int i = 0; i < 4; i++)
                #pragma unroll
                for (int j = 0; j < 4; j++)
                    mma16816(acc[i][j], ahi[i], b[j]);        // Ahi*B

            #pragma unroll
            for (int i = 0; i < 4; i++)
                ldm_x4(alo[i], st + ALO + (uint32_t)(a_row + i * 16) * ROWB + ak);
            #pragma unroll
            for (int i = 0; i < 4; i++)
                #pragma unroll
                for (int j = 0; j < 4; j++)
                    mma16816(acc[i][j], alo[i], b[j]);        // Alo*B
        }
    }
#undef LOAD_STAGE

    // ---------------- epilogue: tanh(acc + bias) ----------------
    #pragma unroll
    for (int j = 0; j < 4; j++) {
        const int col = nBase + warp_n * 32 + j * 8 + (lane & 3) * 2;
        const float bv0 = bias[col], bv1 = bias[col + 1];
        #pragma unroll
        for (int i = 0; i < 4; i++) {
            const int r0 = mBase + warp_m * 64 + i * 16 + (lane >> 2);
            float t00 = tanh_acc(acc[i][j][0] + bv0);
            float t01 = tanh_acc(acc[i][j][1] + bv1);
            float t10 = tanh_acc(acc[i][j][2] + bv0);
            float t11 = tanh_acc(acc[i][j][3] + bv1);
            if (SPLIT_OUT) {
                __half* O = (__half*)Cv;
                __half h00 = __float2half_rn(t00), h01 = __float2half_rn(t01);
                __half h10 = __float2half_rn(t10), h11 = __float2half_rn(t11);
                __half2 h0; h0.x = h00; h0.y = h01;
                __half2 l0; l0.x = __float2half_rn(t00 - __half2float(h00));
                            l0.y = __float2half_rn(t01 - __half2float(h01));
                __half2 h1; h1.x = h10; h1.y = h11;
                __half2 l1; l1.x = __float2half_rn(t10 - __half2float(h10));
                            l1.y = __float2half_rn(t11 - __half2float(h11));
                *(__half2*)&O[(size_t)r0 * KP2 + col]             = h0;
                *(__half2*)&O[(size_t)r0 * KP2 + 512 + col]       = l0;
                *(__half2*)&O[(size_t)(r0 + 8) * KP2 + col]       = h1;
                *(__half2*)&O[(size_t)(r0 + 8) * KP2 + 512 + col] = l1;
            } else {
                float* Cf = (float*)Cv;
                float2 o0, o1;
                o0.x = t00; o0.y = t01; o1.x = t10; o1.y = t11;
                *(float2*)&Cf[(size_t)r0 * Ng + col]       = o0;
                *(float2*)&Cf[(size_t)(r0 + 8) * Ng + col] = o1;
            }
        }
    }
}

// ---------------------------------------------------------------------------
// prep: A1 = [hi | lo] fp16 of (x_a - 0.5)
// ---------------------------------------------------------------------------
__global__ void split_x_kernel(const float* __restrict__ src,
                               __half* __restrict__ dst)
{
    const int idx = blockIdx.x * 256 + threadIdx.x;   // BB*512
    const int b = idx >> 9, s = idx & 511;
    const float v = src[(size_t)b * 1024 + s] - 0.5f;
    const __half hi = __float2half_rn(v);
    __half* d = dst + (size_t)b * KP2;
    d[s] = hi;
    d[512 + s] = __float2half_rn(v - __half2float(hi));
}

// prep: B'[n][k] = fp16(W[k][n])  (transpose, single fp16)
__global__ void wsplit_kernel(const float* __restrict__ W,
                              __half* __restrict__ Bp, int Ncols)
{
    __shared__ float t[32][33];
    const int n0 = blockIdx.x * 32, k0 = blockIdx.y * 32;
    const int tx = threadIdx.x & 31, ty = threadIdx.x >> 5;   // 32 x 8
    #pragma unroll
    for (int j = 0; j < 4; j++)
        t[ty + 8 * j][tx] = W[(size_t)(k0 + ty + 8 * j) * Ncols + n0 + tx];
    __syncthreads();
    #pragma unroll
    for (int j = 0; j < 4; j++) {
        const int n = n0 + ty + 8 * j;
        const int k = k0 + tx;
        Bp[(size_t)n * KB1 + k] = __float2half_rn(t[tx][ty + 8 * j]);
    }
}

// ---------------------------------------------------------------------------
// spline epilogue (validated round 1)
// ---------------------------------------------------------------------------
__global__ __launch_bounds__(512)
void spline_epilogue_kernel(const float* __restrict__ x_input,
                            const float* __restrict__ log_density,
                            const float* __restrict__ net,
                            float* __restrict__ out)
{
    const int b = blockIdx.x;
    const int s = threadIdx.x;

    const float* np = net + (size_t)b * NCC + s * 17;
    float v[17];
    #pragma unroll
    for (int j = 0; j < 17; j++) v[j] = np[j];

    float m = v[9];
    #pragma unroll
    for (int j = 10; j < 17; j++) m = fmaxf(m, v[j]);
    float w[8]; float wsum = 0.f;
    #pragma unroll
    for (int j = 0; j < 8; j++) { w[j] = __expf(v[9 + j] - m); wsum += w[j]; }
    const float winv = 1.f / wsum;
    #pragma unroll
    for (int j = 0; j < 8; j++) w[j] *= winv;

    float eh[9];
    #pragma unroll
    for (int j = 0; j < 9; j++) eh[j] = __expf(v[j]);
    float denom = 0.f;
    #pragma unroll
    for (int i = 0; i < 8; i++) denom += 0.5f * w[i] * (eh[i] + eh[i + 1]);
    const float dinv = 1.f / denom;
    float h[9];
    #pragma unroll
    for (int i = 0; i < 9; i++) h[i] = eh[i] * dinv;

    const float xa = x_input[(size_t)b * 1024 + s];
    const float xb = x_input[(size_t)b * 1024 + 512 + s];

    int cnt = (-EPSK < xb) ? 1 : 0;
    float cs = 0.f;
    #pragma unroll
    for (int i = 0; i < 8; i++) { cs += w[i]; cnt += (cs < xb) ? 1 : 0; }
    int k = cnt - 1;
    k = k < 0 ? 0 : (k > 7 ? 7 : k);

    float xk = 0.f, pk = 0.f, wk = 0.f, hk = 0.f, hk1 = 0.f;
    #pragma unroll
    for (int i = 0; i < 8; i++) {
        const float area = 0.5f * w[i] * (h[i] + h[i + 1]);
        if (i < k)  { xk += w[i]; pk += area; }
        if (i == k) { wk = w[i]; hk = h[i]; hk1 = h[i + 1]; }
    }
    if (k == 0) xk = -EPSK;

    const float alpha = (xb - xk) / wk;
    const float phib  = pk + alpha * hk * wk + 0.5f * alpha * alpha * (hk1 - hk) * wk;
    const float lt    = __logf(fmaf(alpha, (hk1 - hk), hk));

    out[(size_t)b * 1024 + s]       = xa;
    out[(size_t)b * 1024 + 512 + s] = phib;

    __shared__ float red[16];
    float sum = lt;
    #pragma unroll
    for (int o = 16; o > 0; o >>= 1) sum += __shfl_xor_sync(0xffffffffu, sum, o);
    const int lane = s & 31, wid = s >> 5;
    if (lane == 0) red[wid] = sum;
    __syncthreads();
    if (s < 16) {
        float t = red[s];
        #pragma unroll
        for (int o = 8; o > 0; o >>= 1) t += __shfl_xor_sync(0xffffu, t, o);
        if (s == 0) out[(size_t)BB * 1024 + b] = log_density[b] - t;
    }
}

// ---------------------------------------------------------------------------
extern "C" void kernel_launch(void* const* d_in, const int* in_sizes, int n_in,
                              void* d_out, int out_size)
{
    const float* x  = (const float*)d_in[0];
    const float* ld = (const float*)d_in[1];
    const float* W1 = (const float*)d_in[2];
    const float* b1 = (const float*)d_in[3];
    const float* W2 = (const float*)d_in[4];
    const float* b2 = (const float*)d_in[5];
    float* out = (float*)d_out;

    float* net;
    __half *A1, *A2, *B1, *B2;
    cudaGetSymbolAddress((void**)&net, g_net);
    cudaGetSymbolAddress((void**)&A1, g_A1);
    cudaGetSymbolAddress((void**)&A2, g_A2);
    cudaGetSymbolAddress((void**)&B1, g_B1);
    cudaGetSymbolAddress((void**)&B2, g_B2);

    cudaFuncSetAttribute(gemm_tc<true>,  cudaFuncAttributeMaxDynamicSharedMemorySize, DSMEM);
    cudaFuncSetAttribute(gemm_tc<false>, cudaFuncAttributeMaxDynamicSharedMemorySize, DSMEM);

    split_x_kernel<<<BB * 512 / 256, 256>>>(x, A1);
    wsplit_kernel<<<dim3(HH / 32, 512 / 32), 256>>>(W1, B1, HH);
    wsplit_kernel<<<dim3(NCC / 32, 512 / 32), 256>>>(W2, B2, NCC);

    // A2 = split_fp16(tanh((x_a-0.5) @ W1 + b1))   (fused split epilogue)
    gemm_tc<true><<<dim3(HH / 128, BB / 128), 256, DSMEM>>>(A1, B1, b1, A2, HH);
    // net = tanh(hid @ W2 + b2)
    gemm_tc<false><<<dim3(NCC / 128, BB / 128), 256, DSMEM>>>(A2, B2, b2, net, NCC);

    spline_epilogue_kernel<<<BB, 512>>>(x, ld, net, out);
}

// round 10
// speedup vs baseline: 2.2819x; 1.5246x over previous
#include <cuda_runtime.h>
#include <cuda_fp16.h>
#include <stdint.h>
#include <math.h>

#define BB   8192
#define HH   512
#define NCC  8704          // S*(2K+1)
#define EPSK 1e-6f

#define ROWB  80           // 64B data + 16B pad (conflict-free ldsm pitch)
#define NSTG  3

__device__ __align__(128) float  g_net[(size_t)BB * NCC];
__device__ __align__(128) __half g_A1[(size_t)BB * 1024];   // [hi|lo]
__device__ __align__(128) __half g_A2[(size_t)BB * 512];    // single fp16
__device__ __align__(128) __half g_B1[(size_t)HH * 512];
__device__ __align__(128) __half g_B2[(size_t)NCC * 512];

// ------------------------------ helpers ------------------------------------
__device__ __forceinline__ uint32_t smem_u32(const void* p) {
    uint32_t a;
    asm("{ .reg .u64 t; cvta.to.shared.u64 t, %1; cvt.u32.u64 %0, t; }" : "=r"(a) : "l"(p));
    return a;
}
#define CP16(dst, src) \
    asm volatile("cp.async.cg.shared.global [%0], [%1], 16;" :: "r"(dst), "l"(src))
#define CP_COMMIT() asm volatile("cp.async.commit_group;" ::: "memory")
#define CP_WAIT1()  asm volatile("cp.async.wait_group 1;" ::: "memory")

__device__ __forceinline__ void ldm_x4(uint32_t* r, uint32_t addr) {
    asm volatile("ldmatrix.sync.aligned.m8n8.x4.shared.b16 {%0,%1,%2,%3}, [%4];"
                 : "=r"(r[0]), "=r"(r[1]), "=r"(r[2]), "=r"(r[3]) : "r"(addr));
}
__device__ __forceinline__ void mma16816(float* c, const uint32_t* a, const uint32_t* b) {
    asm volatile(
        "mma.sync.aligned.m16n8k16.row.col.f32.f16.f16.f32 "
        "{%0,%1,%2,%3}, {%4,%5,%6,%7}, {%8,%9}, {%0,%1,%2,%3};"
        : "+f"(c[0]), "+f"(c[1]), "+f"(c[2]), "+f"(c[3])
        : "r"(a[0]), "r"(a[1]), "r"(a[2]), "r"(a[3]), "r"(b[0]), "r"(b[1]));
}
__device__ __forceinline__ float tanh_acc(float x) {
    float y = fminf(fmaxf(2.0f * x, -60.0f), 60.0f);
    float t = __expf(y);
    return __fdividef(t - 1.0f, t + 1.0f);
}

// ---------------------------------------------------------------------------
// C[m][n] = tanh( sum_k A[m][k]*B[n][k] + bias[n] )
// APASS=2: A stored [hi(512)|lo(512)] fp16 (row stride 1024), 2 mma passes.
// APASS=1: A stored single fp16 (row stride 512), 1 mma pass.
// B stored fp16 (row stride 512). CTA 128x128, 256 thr, warp tile 64x32,
// BK=32, 3-stage cp.async, ONE __syncthreads/iter, 2 CTAs/SM.
// OUT_F16: write single fp16 (stride 512) instead of fp32 (stride Ng).
// ---------------------------------------------------------------------------
template <int APASS, bool OUT_F16>
__global__ __launch_bounds__(256, 2)
void gemm_tc(const __half* __restrict__ A, const __half* __restrict__ Bm,
             const float* __restrict__ bias, void* __restrict__ Cv, int Ng)
{
    constexpr uint32_t ALO  = 128 * ROWB;            // only used when APASS==2
    constexpr uint32_t BRG  = APASS * 128 * ROWB;
    constexpr uint32_t STG  = (APASS + 1) * 128 * ROWB;
    constexpr int AROWB     = APASS * 1024;           // A global row bytes

    extern __shared__ char dyn[];
    const uint32_t dynB = smem_u32(dyn);
    const int tid  = threadIdx.x;
    const int lane = tid & 31, w = tid >> 5;
    const int warp_m = w & 1, warp_n = w >> 1;        // 2 x 4
    const int mBase = blockIdx.y * 128, nBase = blockIdx.x * 128;

    const char* Ag = (const char*)A + (size_t)mBase * AROWB;
    const char* Bg = (const char*)(Bm + (size_t)nBase * 512);

    const int lrow = tid >> 2;          // 0..63 (+64 second pass)
    const int lch  = (tid & 3) * 16;    // 4 thr x 16B = 64B = BK

#define LOAD_STAGE(c) do {                                                        \
    const uint32_t _s = dynB + ((c) % 3) * STG;                                   \
    const size_t _kb = (size_t)(c) * 64;                                          \
    _Pragma("unroll")                                                             \
    for (int _h = 0; _h < 2; _h++) {                                              \
        const int _r = lrow + _h * 64;                                            \
        const size_t _ra = (size_t)_r * AROWB;                                    \
        CP16(_s + _r * ROWB + lch, Ag + _ra + _kb + lch);                         \
        if (APASS == 2)                                                           \
            CP16(_s + ALO + _r * ROWB + lch, Ag + _ra + 1024 + _kb + lch);        \
        CP16(_s + BRG + _r * ROWB + lch, Bg + (size_t)_r * 1024 + _kb + lch);     \
    }                                                                             \
} while (0)

    LOAD_STAGE(0); CP_COMMIT();
    LOAD_STAGE(1); CP_COMMIT();

    float acc[4][4][4];
    #pragma unroll
    for (int i = 0; i < 4; i++)
        #pragma unroll
        for (int j = 0; j < 4; j++)
            #pragma unroll
            for (int e = 0; e < 4; e++) acc[i][j][e] = 0.f;

    const int grp = lane >> 3, lr = lane & 7;
    const int a_row = warp_m * 64 + (grp & 1) * 8 + lr;
    const int a_kb  = (grp >> 1) * 16;
    const int b_row = warp_n * 32 + (grp >> 1) * 8 + lr;
    const int b_kb  = (grp & 1) * 16;

    const int NIT = 512 / 32;   // 16
    for (int c = 0; c < NIT; c++) {
        CP_WAIT1();               // stage c resident (c+1 in flight)
        __syncthreads();          // buffer (c+2)%3 free (consumed at iter c-1)
        if (c + 2 < NIT) LOAD_STAGE(c + 2);
        CP_COMMIT();              // uniform group count

        const uint32_t st = dynB + (c % 3) * STG;

        #pragma unroll
        for (int kk = 0; kk < 2; kk++) {
            const uint32_t ak = kk * 32 + a_kb;
            const uint32_t bk = kk * 32 + b_kb;
            uint32_t ahi[4][4], b[4][2];

            #pragma unroll
            for (int i = 0; i < 4; i++)
                ldm_x4(ahi[i], st + (uint32_t)(a_row + i * 16) * ROWB + ak);
            #pragma unroll
            for (int p = 0; p < 2; p++) {
                uint32_t r[4];
                ldm_x4(r, st + BRG + (uint32_t)(b_row + p * 16) * ROWB + bk);
                b[p * 2][0] = r[0]; b[p * 2][1] = r[1];
                b[p * 2 + 1][0] = r[2]; b[p * 2 + 1][1] = r[3];
            }
            #pragma unroll
            for (int i = 0; i < 4; i++)
                #pragma unroll
                for (int j = 0; j < 4; j++)
                    mma16816(acc[i][j], ahi[i], b[j]);        // Ahi*B

            if (APASS == 2) {
                uint32_t alo[4][4];
                #pragma unroll
                for (int i = 0; i < 4; i++)
                    ldm_x4(alo[i], st + ALO + (uint32_t)(a_row + i * 16) * ROWB + ak);
                #pragma unroll
                for (int i = 0; i < 4; i++)
                    #pragma unroll
                    for (int j = 0; j < 4; j++)
                        mma16816(acc[i][j], alo[i], b[j]);    // Alo*B
            }
        }
    }
#undef LOAD_STAGE

    // ---------------- epilogue: tanh(acc + bias) ----------------
    #pragma unroll
    for (int j = 0; j < 4; j++) {
        const int col = nBase + warp_n * 32 + j * 8 + (lane & 3) * 2;
        const float bv0 = bias[col], bv1 = bias[col + 1];
        #pragma unroll
        for (int i = 0; i < 4; i++) {
            const int r0 = mBase + warp_m * 64 + i * 16 + (lane >> 2);
            float t00 = tanh_acc(acc[i][j][0] + bv0);
            float t01 = tanh_acc(acc[i][j][1] + bv1);
            float t10 = tanh_acc(acc[i][j][2] + bv0);
            float t11 = tanh_acc(acc[i][j][3] + bv1);
            if (OUT_F16) {
                __half* O = (__half*)Cv;
                __half2 h0; h0.x = __float2half_rn(t00); h0.y = __float2half_rn(t01);
                __half2 h1; h1.x = __float2half_rn(t10); h1.y = __float2half_rn(t11);
                *(__half2*)&O[(size_t)r0 * 512 + col]       = h0;
                *(__half2*)&O[(size_t)(r0 + 8) * 512 + col] = h1;
            } else {
                float* Cf = (float*)Cv;
                float2 o0, o1;
                o0.x = t00; o0.y = t01; o1.x = t10; o1.y = t11;
                *(float2*)&Cf[(size_t)r0 * Ng + col]       = o0;
                *(float2*)&Cf[(size_t)(r0 + 8) * Ng + col] = o1;
            }
        }
    }
}

// ---------------------------------------------------------------------------
// prep: A1 = [hi | lo] fp16 of (x_a - 0.5)
// ---------------------------------------------------------------------------
__global__ void split_x_kernel(const float* __restrict__ src,
                               __half* __restrict__ dst)
{
    const int idx = blockIdx.x * 256 + threadIdx.x;   // BB*512
    const int b = idx >> 9, s = idx & 511;
    const float v = src[(size_t)b * 1024 + s] - 0.5f;
    const __half hi = __float2half_rn(v);
    __half* d = dst + (size_t)b * 1024;
    d[s] = hi;
    d[512 + s] = __float2half_rn(v - __half2float(hi));
}

// prep: B'[n][k] = fp16(W[k][n])  (transpose, single fp16)
__global__ void wsplit_kernel(const float* __restrict__ W,
                              __half* __restrict__ Bp, int Ncols)
{
    __shared__ float t[32][33];
    const int n0 = blockIdx.x * 32, k0 = blockIdx.y * 32;
    const int tx = threadIdx.x & 31, ty = threadIdx.x >> 5;   // 32 x 8
    #pragma unroll
    for (int j = 0; j < 4; j++)
        t[ty + 8 * j][tx] = W[(size_t)(k0 + ty + 8 * j) * Ncols + n0 + tx];
    __syncthreads();
    #pragma unroll
    for (int j = 0; j < 4; j++) {
        const int n = n0 + ty + 8 * j;
        const int k = k0 + tx;
        Bp[(size_t)n * 512 + k] = __float2half_rn(t[tx][ty + 8 * j]);
    }
}

// ---------------------------------------------------------------------------
// spline epilogue (validated round 1)
// ---------------------------------------------------------------------------
__global__ __launch_bounds__(512)
void spline_epilogue_kernel(const float* __restrict__ x_input,
                            const float* __restrict__ log_density,
                            const float* __restrict__ net,
                            float* __restrict__ out)
{
    const int b = blockIdx.x;
    const int s = threadIdx.x;

    const float* np = net + (size_t)b * NCC + s * 17;
    float v[17];
    #pragma unroll
    for (int j = 0; j < 17; j++) v[j] = np[j];

    float m = v[9];
    #pragma unroll
    for (int j = 10; j < 17; j++) m = fmaxf(m, v[j]);
    float w[8]; float wsum = 0.f;
    #pragma unroll
    for (int j = 0; j < 8; j++) { w[j] = __expf(v[9 + j] - m); wsum += w[j]; }
    const float winv = 1.f / wsum;
    #pragma unroll
    for (int j = 0; j < 8; j++) w[j] *= winv;

    float eh[9];
    #pragma unroll
    for (int j = 0; j < 9; j++) eh[j] = __expf(v[j]);
    float denom = 0.f;
    #pragma unroll
    for (int i = 0; i < 8; i++) denom += 0.5f * w[i] * (eh[i] + eh[i + 1]);
    const float dinv = 1.f / denom;
    float h[9];
    #pragma unroll
    for (int i = 0; i < 9; i++) h[i] = eh[i] * dinv;

    const float xa = x_input[(size_t)b * 1024 + s];
    const float xb = x_input[(size_t)b * 1024 + 512 + s];

    int cnt = (-EPSK < xb) ? 1 : 0;
    float cs = 0.f;
    #pragma unroll
    for (int i = 0; i < 8; i++) { cs += w[i]; cnt += (cs < xb) ? 1 : 0; }
    int k = cnt - 1;
    k = k < 0 ? 0 : (k > 7 ? 7 : k);

    float xk = 0.f, pk = 0.f, wk = 0.f, hk = 0.f, hk1 = 0.f;
    #pragma unroll
    for (int i = 0; i < 8; i++) {
        const float area = 0.5f * w[i] * (h[i] + h[i + 1]);
        if (i < k)  { xk += w[i]; pk += area; }
        if (i == k) { wk = w[i]; hk = h[i]; hk1 = h[i + 1]; }
    }
    if (k == 0) xk = -EPSK;

    const float alpha = (xb - xk) / wk;
    const float phib  = pk + alpha * hk * wk + 0.5f * alpha * alpha * (hk1 - hk) * wk;
    const float lt    = __logf(fmaf(alpha, (hk1 - hk), hk));

    out[(size_t)b * 1024 + s]       = xa;
    out[(size_t)b * 1024 + 512 + s] = phib;

    __shared__ float red[16];
    float sum = lt;
    #pragma unroll
    for (int o = 16; o > 0; o >>= 1) sum += __shfl_xor_sync(0xffffffffu, sum, o);
    const int lane = s & 31, wid = s >> 5;
    if (lane == 0) red[wid] = sum;
    __syncthreads();
    if (s < 16) {
        float t = red[s];
        #pragma unroll
        for (int o = 8; o > 0; o >>= 1) t += __shfl_xor_sync(0xffffu, t, o);
        if (s == 0) out[(size_t)BB * 1024 + b] = log_density[b] - t;
    }
}

// ---------------------------------------------------------------------------
extern "C" void kernel_launch(void* const* d_in, const int* in_sizes, int n_in,
                              void* d_out, int out_size)
{
    const float* x  = (const float*)d_in[0];
    const float* ld = (const float*)d_in[1];
    const float* W1 = (const float*)d_in[2];
    const float* b1 = (const float*)d_in[3];
    const float* W2 = (const float*)d_in[4];
    const float* b2 = (const float*)d_in[5];
    float* out = (float*)d_out;

    float* net;
    __half *A1, *A2, *B1, *B2;
    cudaGetSymbolAddress((void**)&net, g_net);
    cudaGetSymbolAddress((void**)&A1, g_A1);
    cudaGetSymbolAddress((void**)&A2, g_A2);
    cudaGetSymbolAddress((void**)&B1, g_B1);
    cudaGetSymbolAddress((void**)&B2, g_B2);

    const int DS1 = NSTG * 3 * 128 * ROWB;   // APASS=2 stage: 30720 * 3
    const int DS2 = NSTG * 2 * 128 * ROWB;   // APASS=1 stage: 20480 * 3
    cudaFuncSetAttribute((const void*)gemm_tc<2, true>,
                         cudaFuncAttributeMaxDynamicSharedMemorySize, DS1);
    cudaFuncSetAttribute((const void*)gemm_tc<1, false>,
                         cudaFuncAttributeMaxDynamicSharedMemorySize, DS2);

    split_x_kernel<<<BB * 512 / 256, 256>>>(x, A1);
    wsplit_kernel<<<dim3(HH / 32, 512 / 32), 256>>>(W1, B1, HH);
    wsplit_kernel<<<dim3(NCC / 32, 512 / 32), 256>>>(W2, B2, NCC);

    // A2 = fp16(tanh((x_a-0.5) @ W1 + b1)) — accurate 2-pass GEMM, fp16 out
    gemm_tc<2, true><<<dim3(HH / 128, BB / 128), 256, DS1>>>(A1, B1, b1, A2, HH);
    // net = tanh(hid @ W2 + b2) — single-pass fp16
    gemm_tc<1, false><<<dim3(NCC / 128, BB / 128), 256, DS2>>>(A2, B2, b2, net, NCC);

    spline_epilogue_kernel<<<BB, 512>>>(x, ld, net, out);
}